// round 13
// baseline (speedup 1.0000x reference)
#include <cuda_runtime.h>
#include <cuda_fp16.h>
#include <cstdint>
#include <math.h>

#define S_LEN 4096
#define C_DIM 1024
#define H_NUM 16
#define HD    64
// Q pre-scale: 1/sqrt(64) * log2(e)  (softmax runs in exp2 domain)
#define QSCALE 0.18033688011112042f

// Scratch (__device__ globals). All mma-fragment-packed, fp16.
__device__ uint32_t g_qp [(size_t)H_NUM * 256 * 4 * 32 * 4];   // Q A-perm16 per head
__device__ uint32_t g_kp [(size_t)H_NUM * 512 * 4 * 32 * 2];   // K B-perm16 per head
__device__ __half   g_vp [(size_t)H_NUM * 256 * 8 * 32 * 4];   // V B-perm16 (kv-major)
__device__ uint32_t g_att[(size_t)256 * 64 * 32 * 4];          // attn out, A-perm16
__device__ uint32_t g_xp [(size_t)256 * 64 * 32 * 4];          // x, A-perm16
__device__ uint32_t g_wtp[(size_t)384 * 64 * 32 * 2];          // W_attn B-perm16 (Q pre-scaled)
__device__ uint32_t g_wpp[(size_t)128 * 64 * 32 * 2];          // W_proj B-perm16

// ---------------------------------------------------------------------------
__device__ __forceinline__ void cp16(void* s, const void* g) {
    uint32_t sa = (uint32_t)__cvta_generic_to_shared(s);
    asm volatile("cp.async.cg.shared.global [%0], [%1], 16;"
                 :: "r"(sa), "l"(__cvta_generic_to_global(g)));
}

__device__ __forceinline__ uint32_t h2u(__half2 h) {
    return *reinterpret_cast<uint32_t*>(&h);
}

__device__ __forceinline__ float ex2(float x) {
    float y;
    asm("ex2.approx.ftz.f32 %0, %1;" : "=f"(y) : "f"(x));
    return y;
}

// m16n8k16 fp16 mma, fp32 accum. A row-major, B col-major.
__device__ __forceinline__ void mma_f16(float c[4], const uint32_t a[4],
                                        uint32_t b0, uint32_t b1) {
    asm volatile(
        "mma.sync.aligned.m16n8k16.row.col.f32.f16.f16.f32 "
        "{%0,%1,%2,%3}, {%4,%5,%6,%7}, {%8,%9}, {%0,%1,%2,%3};"
        : "+f"(c[0]), "+f"(c[1]), "+f"(c[2]), "+f"(c[3])
        : "r"(a[0]), "r"(a[1]), "r"(a[2]), "r"(a[3]), "r"(b0), "r"(b1));
}

// ---------------------------------------------------------------------------
// Prep: A-perm16 of x [M,K]f32 -> [mb][kb16][lane][4xb32(h2)]
// ---------------------------------------------------------------------------
__global__ __launch_bounds__(256) void permA16_kernel(
    const float* __restrict__ in, uint32_t* __restrict__ out, int M, int K)
{
    int cid = blockIdx.x * 256 + threadIdx.x;
    if (cid >= (M / 16) * (K / 16) * 32) return;
    const int per_mb = (K >> 4) * 32;
    int mb  = cid / per_mb;
    int rem = cid - mb * per_mb;
    int kb  = rem >> 5;
    int lane = rem & 31;
    int g = lane >> 2, q = lane & 3;
    size_t r = mb * 16 + g, c = kb * 16 + 2 * q;
    uint4 o;
    o.x = h2u(__floats2half2_rn(in[r * K + c],           in[r * K + c + 1]));
    o.y = h2u(__floats2half2_rn(in[(r + 8) * K + c],     in[(r + 8) * K + c + 1]));
    o.z = h2u(__floats2half2_rn(in[r * K + c + 8],       in[r * K + c + 9]));
    o.w = h2u(__floats2half2_rn(in[(r + 8) * K + c + 8], in[(r + 8) * K + c + 9]));
    ((uint4*)out)[cid] = o;
}

// ---------------------------------------------------------------------------
// Prep: B-perm16 of W [K][N] -> [nb][kb16][lane][2xb32]; cols n<scaleN *= scale
// ---------------------------------------------------------------------------
__global__ __launch_bounds__(256) void permB16_kernel(
    const float* __restrict__ W, uint32_t* __restrict__ out,
    int K, int N, int scaleN, float scale)
{
    int cid = blockIdx.x * 256 + threadIdx.x;
    if (cid >= (N / 8) * (K / 16) * 32) return;
    const int per_nb = (K >> 4) * 32;
    int nb  = cid / per_nb;
    int rem = cid - nb * per_nb;
    int kb  = rem >> 5;
    int lane = rem & 31;
    int g = lane >> 2, q = lane & 3;
    size_t n = nb * 8 + g, k = kb * 16 + 2 * q;
    float s = (n < (size_t)scaleN) ? scale : 1.f;
    uint2 o;
    o.x = h2u(__floats2half2_rn(W[k * N + n] * s,       W[(k + 1) * N + n] * s));
    o.y = h2u(__floats2half2_rn(W[(k + 8) * N + n] * s, W[(k + 9) * N + n] * s));
    ((uint2*)out)[cid] = o;
}

// ---------------------------------------------------------------------------
// fp16 mma.sync GEMM, CTA 128x128, 128 threads (4 warps 2x2), warp 64x64.
// BK=32 (2 kb16), 3-stage cp.async. (unchanged)
// ---------------------------------------------------------------------------
#define GSTAGE_U 4096
#define GSMEM_DYN (3 * GSTAGE_U * 4)

extern __shared__ uint32_t gsm[];

template<int MODE>
__global__ __launch_bounds__(128, 2) void gemm_f16_kernel(
    int M, int N, int K,
    const uint32_t* __restrict__ Ap,
    const uint32_t* __restrict__ Bp,
    const float* __restrict__ bias,
    float* __restrict__ C,
    uint32_t* __restrict__ Qp,
    uint32_t* __restrict__ Kp,
    __half* __restrict__ Vp)
{
    const int tid  = threadIdx.x;
    const int wid  = tid >> 5;
    const int lane = tid & 31;
    const int g    = lane >> 2, q = lane & 3;
    const int bm   = blockIdx.y * 128;
    const int bn   = blockIdx.x * 128;
    const int mb0  = (wid >> 1) * 4;
    const int nb0  = (wid & 1) * 8;
    const int KB   = K >> 4;
    const int nch  = K >> 5;

    float acc[4][8][4];
#pragma unroll
    for (int i = 0; i < 4; i++)
#pragma unroll
        for (int j = 0; j < 8; j++)
#pragma unroll
            for (int e = 0; e < 4; e++) acc[i][j][e] = 0.f;

    auto load_stage = [&](int s, int ch) {
        uint32_t* As = gsm + s * GSTAGE_U;
        uint32_t* Bs = As + 2048;
        const int kb0 = ch * 2;
#pragma unroll
        for (int it = 0; it < 4; it++) {
            int idx = tid + it * 128;
            int mb = idx >> 6, rem = idx & 63;
            int kb = rem >> 5, l = rem & 31;
            const uint32_t* src = Ap +
                ((size_t)((bm >> 4) + mb) * KB + kb0 + kb) * 128 + l * 4;
            cp16(As + idx * 4, src);
        }
#pragma unroll
        for (int it = 0; it < 4; it++) {
            int idx = tid + it * 128;
            int nb = idx >> 5, rem = idx & 31;
            int kb = rem >> 4, ll = rem & 15;
            const uint32_t* src = Bp +
                ((size_t)((bn >> 3) + nb) * KB + kb0 + kb) * 64 + ll * 4;
            cp16(Bs + idx * 4, src);
        }
        asm volatile("cp.async.commit_group;" ::: "memory");
    };

    load_stage(0, 0);
    load_stage(1, 1);

    for (int ch = 0; ch < nch; ch++) {
        if (ch + 2 < nch)
            asm volatile("cp.async.wait_group 1;" ::: "memory");
        else
            asm volatile("cp.async.wait_group 0;" ::: "memory");
        __syncthreads();

        if (ch + 2 < nch) load_stage((ch + 2) % 3, ch + 2);

        const uint32_t* As = gsm + (ch % 3) * GSTAGE_U;
        const uint32_t* Bs = As + 2048;

#pragma unroll
        for (int kb = 0; kb < 2; kb++) {
            uint4 afr[4];
            uint2 bfr[8];
#pragma unroll
            for (int i = 0; i < 4; i++)
                afr[i] = *(const uint4*)(As + ((mb0 + i) * 2 + kb) * 128 + lane * 4);
#pragma unroll
            for (int j = 0; j < 8; j++)
                bfr[j] = *(const uint2*)(Bs + ((nb0 + j) * 2 + kb) * 64 + lane * 2);
#pragma unroll
            for (int i = 0; i < 4; i++)
#pragma unroll
                for (int j = 0; j < 8; j++)
                    mma_f16(acc[i][j], (const uint32_t*)&afr[i], bfr[j].x, bfr[j].y);
        }
    }

    if (MODE == 0) {
#pragma unroll
        for (int j = 0; j < 8; j++) {
            const int col = bn + (wid & 1) * 64 + j * 8 + 2 * q;
            const float2 bv = *(const float2*)(bias + col);
#pragma unroll
            for (int i = 0; i < 4; i++) {
                const int r0 = bm + (wid >> 1) * 64 + i * 16 + g;
                float2 o0, o1;
                o0.x = acc[i][j][0] + bv.x;
                o0.y = acc[i][j][1] + bv.y;
                o1.x = acc[i][j][2] + bv.x;
                o1.y = acc[i][j][3] + bv.y;
                *(float2*)(C + (size_t)r0 * N + col) = o0;
                *(float2*)(C + (size_t)(r0 + 8) * N + col) = o1;
            }
        }
    } else {
        const int sec = bn >> 10;
        const int hh  = ((bn & 1023) >> 6) + (wid & 1);
        const float bscale = (sec == 0) ? QSCALE : 1.f;
#pragma unroll
        for (int j = 0; j < 8; j++) {
            const int col = bn + (wid & 1) * 64 + j * 8 + 2 * q;
            float2 bv = *(const float2*)(bias + col);
            bv.x *= bscale; bv.y *= bscale;
#pragma unroll
            for (int i = 0; i < 4; i++) {
                float v00 = acc[i][j][0] + bv.x;
                float v01 = acc[i][j][1] + bv.y;
                float v10 = acc[i][j][2] + bv.x;
                float v11 = acc[i][j][3] + bv.y;
                uint32_t p0 = h2u(__floats2half2_rn(v00, v01));
                uint32_t p1 = h2u(__floats2half2_rn(v10, v11));
                if (sec == 0) {
                    const int mb = (bm >> 4) + (wid >> 1) * 4 + i;
                    const int kb = j >> 1;
                    uint32_t* base = Qp +
                        (((size_t)(hh * 256 + mb) * 4 + kb) * 32 + lane) * 4 + (j & 1) * 2;
                    base[0] = p0;
                    base[1] = p1;
                } else if (sec == 1) {
                    const int nb = (bm >> 3) + (wid >> 1) * 8 + i * 2;
                    const int kb = j >> 1;
                    uint32_t* base = Kp +
                        (((size_t)(hh * 512 + nb) * 4 + kb) * 32 + lane) * 2 + (j & 1);
                    base[0]   = p0;
                    base[256] = p1;
                } else {
                    const int kvb = (bm >> 4) + (wid >> 1) * 4 + i;
                    const int hi  = g & 1;
                    __half* b0 = Vp +
                        ((((size_t)(hh * 256 + kvb) * 8 + j) * 32 + 2 * q * 4 + (g >> 1)) * 4);
                    __half* b1 = b0 + 16;
                    b0[hi]     = __float2half_rn(v00);
                    b0[2 + hi] = __float2half_rn(v10);
                    b1[hi]     = __float2half_rn(v01);
                    b1[2 + hi] = __float2half_rn(v11);
                }
            }
        }
    }
}

// ---------------------------------------------------------------------------
// Causal flash attention, fp16 m16n8k16, exp2 softmax, SOFTWARE-PIPELINED:
// round jt issues PV(jt) interleaved with QK(jt+1) (one fused mma block),
// then softmax(jt+1). P-pack frees sv so QK reuses it (register parity).
// 4-stage shared KV ring; wait_group(1) guarantees tile jt+1 (in-order => jt).
// Stage reuse: load(jt+3) overwrites tile jt-1, last read in round jt-1,
// protected by this round's single __syncthreads.
// ---------------------------------------------------------------------------
#define ASTG_U 4096                          // u32 per stage: K 2048 + V 2048
#define ASMEM_DYN (4 * ASTG_U * 4)           // 65536 B

extern __shared__ uint32_t asmem[];

__global__ __launch_bounds__(256, 2) void attn_f16_kernel(
    const uint32_t* __restrict__ Qp, const uint32_t* __restrict__ Kp,
    const uint32_t* __restrict__ Vp, uint32_t* __restrict__ att)
{
    const int tid   = threadIdx.x;
    const int warp  = tid >> 5;
    const int lane  = tid & 31;
    const int grp   = lane >> 2;
    const int qd    = lane & 3;
    const int h     = blockIdx.y;
    const int qtile = gridDim.x - 1 - blockIdx.x;
    const int qbase = qtile * 128;
    const int qr0   = warp * 16 + grp;
    const int njt   = 2 * qtile + 2;

    // ---- Q fragments: 4 x LDG.128 from packed Qp ----
    uint32_t qa[4][4];
    {
        const uint4* Qb = (const uint4*)(Qp +
            ((size_t)(h * 256 + qtile * 8 + warp) * 4) * 128);
#pragma unroll
        for (int ks = 0; ks < 4; ks++) {
            uint4 v = Qb[ks * 32 + lane];
            qa[ks][0] = v.x; qa[ks][1] = v.y; qa[ks][2] = v.z; qa[ks][3] = v.w;
        }
    }

    // shared load of tile jt into stage jt%4 (empty commit past the end)
    auto load_kv = [&](int jt) {
        if (jt < njt) {
            uint32_t* Ks = asmem + (jt & 3) * ASTG_U;
            uint32_t* Vs = Ks + 2048;
            const uint32_t* Kg = Kp + (size_t)(h * 512 + jt * 8) * 256;
            const uint32_t* Vg = Vp + (size_t)(h * 256 + jt * 4) * 512;
#pragma unroll
            for (int it = 0; it < 2; it++) {
                int idx = tid + it * 256;
                cp16(Ks + idx * 4, Kg + idx * 4);
                cp16(Vs + idx * 4, Vg + idx * 4);
            }
        }
        asm volatile("cp.async.commit_group;" ::: "memory");
    };

    load_kv(0);
    load_kv(1);
    load_kv(2);

    float o[8][4];
#pragma unroll
    for (int nt = 0; nt < 8; nt++)
#pragma unroll
        for (int e = 0; e < 4; e++) o[nt][e] = 0.f;
    float m0 = -INFINITY, m1 = -INFINITY, l0 = 0.f, l1 = 0.f;

    float sv[8][4];          // QK accumulator / softmax'd P values (pre-pack)
    uint32_t p0[8], p1[8];   // packed P fragments for PV

    // softmax of tile t held in sv (exp2 domain, online rescale of o)
    auto softmax_tile = [&](int t) {
        if (t >= 2 * qtile) {                   // causal boundary tiles
            const int kvbase = t * 64;
            const int rg0 = qbase + qr0, rg1 = rg0 + 8;
#pragma unroll
            for (int nt = 0; nt < 8; nt++) {
                int cg = kvbase + nt * 8 + qd * 2;
                if (cg     > rg0) sv[nt][0] = -INFINITY;
                if (cg + 1 > rg0) sv[nt][1] = -INFINITY;
                if (cg     > rg1) sv[nt][2] = -INFINITY;
                if (cg + 1 > rg1) sv[nt][3] = -INFINITY;
            }
        }
        float mt0 = -INFINITY, mt1 = -INFINITY;
#pragma unroll
        for (int nt = 0; nt < 8; nt++) {
            mt0 = fmaxf(mt0, fmaxf(sv[nt][0], sv[nt][1]));
            mt1 = fmaxf(mt1, fmaxf(sv[nt][2], sv[nt][3]));
        }
        mt0 = fmaxf(mt0, __shfl_xor_sync(0xffffffffu, mt0, 1));
        mt0 = fmaxf(mt0, __shfl_xor_sync(0xffffffffu, mt0, 2));
        mt1 = fmaxf(mt1, __shfl_xor_sync(0xffffffffu, mt1, 1));
        mt1 = fmaxf(mt1, __shfl_xor_sync(0xffffffffu, mt1, 2));

        const float mn0 = fmaxf(m0, mt0), mn1 = fmaxf(m1, mt1);
        const float al0 = ex2(m0 - mn0), al1 = ex2(m1 - mn1);
        m0 = mn0; m1 = mn1;

        float rs0 = 0.f, rs1 = 0.f;
#pragma unroll
        for (int nt = 0; nt < 8; nt++) {
            sv[nt][0] = ex2(sv[nt][0] - mn0);
            sv[nt][1] = ex2(sv[nt][1] - mn0);
            sv[nt][2] = ex2(sv[nt][2] - mn1);
            sv[nt][3] = ex2(sv[nt][3] - mn1);
            rs0 += sv[nt][0] + sv[nt][1];
            rs1 += sv[nt][2] + sv[nt][3];
        }
        rs0 += __shfl_xor_sync(0xffffffffu, rs0, 1);
        rs0 += __shfl_xor_sync(0xffffffffu, rs0, 2);
        rs1 += __shfl_xor_sync(0xffffffffu, rs1, 1);
        rs1 += __shfl_xor_sync(0xffffffffu, rs1, 2);
        l0 = l0 * al0 + rs0;
        l1 = l1 * al1 + rs1;

#pragma unroll
        for (int nt = 0; nt < 8; nt++) {
            o[nt][0] *= al0; o[nt][1] *= al0;
            o[nt][2] *= al1; o[nt][3] *= al1;
        }
    };

    // ---- prologue: QK(0) + softmax(0) ----
    asm volatile("cp.async.wait_group 2;" ::: "memory");
    __syncthreads();
    {
        const uint32_t* Ks = asmem;   // stage 0
#pragma unroll
        for (int nt = 0; nt < 8; nt++)
#pragma unroll
            for (int e = 0; e < 4; e++) sv[nt][e] = 0.f;
#pragma unroll
        for (int ks = 0; ks < 4; ks++)
#pragma unroll
            for (int nt = 0; nt < 8; nt++) {
                uint2 b = *(const uint2*)(Ks + ((nt * 4 + ks) * 32 + lane) * 2);
                mma_f16(sv[nt], qa[ks], b.x, b.y);
            }
        softmax_tile(0);
    }

    // ---- main loop: round jt = PV(jt) fused with QK(jt+1), then softmax ----
    for (int jt = 0; jt < njt; jt++) {
        // pack P(jt) -> frees sv for QK(jt+1)
#pragma unroll
        for (int nt = 0; nt < 8; nt++) {
            p0[nt] = h2u(__floats2half2_rn(sv[nt][0], sv[nt][1]));
            p1[nt] = h2u(__floats2half2_rn(sv[nt][2], sv[nt][3]));
        }

        asm volatile("cp.async.wait_group 1;" ::: "memory");
        __syncthreads();
        load_kv(jt + 3);

        const uint32_t* Vs = asmem + (jt & 3) * ASTG_U + 2048;
        const uint32_t* Kn = asmem + ((jt + 1) & 3) * ASTG_U;
        const bool more = (jt + 1 < njt);

        if (more) {
#pragma unroll
            for (int nt = 0; nt < 8; nt++)
#pragma unroll
                for (int e = 0; e < 4; e++) sv[nt][e] = 0.f;
        }

        // fused mma block: PV(jt) + QK(jt+1) interleaved
#pragma unroll
        for (int ks = 0; ks < 4; ks++) {
            uint32_t pa[4] = { p0[2 * ks], p1[2 * ks],
                               p0[2 * ks + 1], p1[2 * ks + 1] };
#pragma unroll
            for (int nt = 0; nt < 8; nt++) {
                uint2 b = *(const uint2*)(Vs + ((ks * 8 + nt) * 32 + lane) * 2);
                mma_f16(o[nt], pa, b.x, b.y);
            }
            if (more) {
#pragma unroll
                for (int nt = 0; nt < 8; nt++) {
                    uint2 b = *(const uint2*)(Kn + ((nt * 4 + ks) * 32 + lane) * 2);
                    mma_f16(sv[nt], qa[ks], b.x, b.y);
                }
            }
        }

        if (more) softmax_tile(jt + 1);
    }

    // ---- epilogue: normalize + fp16 round, store g_att in A-perm16 ----
    const float i0 = 1.f / l0, i1 = 1.f / l1;
    const int mb = qtile * 8 + warp;
#pragma unroll
    for (int nt = 0; nt < 8; nt++) {
        const int kb = h * 4 + (nt >> 1);
        uint32_t* base = att +
            (((size_t)mb * 64 + kb) * 32 + lane) * 4 + (nt & 1) * 2;
        base[0] = h2u(__floats2half2_rn(o[nt][0] * i0, o[nt][1] * i0));
        base[1] = h2u(__floats2half2_rn(o[nt][2] * i1, o[nt][3] * i1));
    }
}

// ---------------------------------------------------------------------------
// Launch
// ---------------------------------------------------------------------------
extern "C" void kernel_launch(void* const* d_in, const int* in_sizes, int n_in,
                              void* d_out, int out_size)
{
    const float* x      = (const float*)d_in[0];
    // d_in[1] = attention_mask: exact causal triu -> handled analytically
    const float* W_attn = (const float*)d_in[2];
    const float* b_attn = (const float*)d_in[3];
    const float* W_proj = (const float*)d_in[4];
    const float* b_proj = (const float*)d_in[5];
    float* out = (float*)d_out;

    uint32_t *qp_p, *kp_p, *att_p, *xp_p, *wtp_p, *wpp_p;
    __half* vp_p;
    cudaGetSymbolAddress((void**)&qp_p,  g_qp);
    cudaGetSymbolAddress((void**)&kp_p,  g_kp);
    cudaGetSymbolAddress((void**)&vp_p,  g_vp);
    cudaGetSymbolAddress((void**)&att_p, g_att);
    cudaGetSymbolAddress((void**)&xp_p,  g_xp);
    cudaGetSymbolAddress((void**)&wtp_p, g_wtp);
    cudaGetSymbolAddress((void**)&wpp_p, g_wpp);

    // 0) prep: fp16 permuted operands (Q cols of W_attn get QSCALE)
    {
        int nA = 256 * 64 * 32;
        permA16_kernel<<<(nA + 255) / 256, 256>>>(x, xp_p, S_LEN, C_DIM);

        int nB1 = 384 * 64 * 32;
        permB16_kernel<<<(nB1 + 255) / 256, 256>>>(
            W_attn, wtp_p, C_DIM, 3 * C_DIM, C_DIM, QSCALE);

        int nB2 = 128 * 64 * 32;
        permB16_kernel<<<(nB2 + 255) / 256, 256>>>(
            W_proj, wpp_p, C_DIM, C_DIM, 0, 1.f);
    }

    cudaFuncSetAttribute(gemm_f16_kernel<0>,
                         cudaFuncAttributeMaxDynamicSharedMemorySize, GSMEM_DYN);
    cudaFuncSetAttribute(gemm_f16_kernel<1>,
                         cudaFuncAttributeMaxDynamicSharedMemorySize, GSMEM_DYN);

    // 1) qkv GEMM -> packed Qp/Kp/Vp
    {
        dim3 grid((3 * C_DIM) / 128, S_LEN / 128);
        gemm_f16_kernel<1><<<grid, 128, GSMEM_DYN>>>(
            S_LEN, 3 * C_DIM, C_DIM, xp_p, wtp_p, b_attn,
            nullptr, qp_p, kp_p, vp_p);
    }

    // 2) causal flash attention (software-pipelined PV+QK)
    {
        cudaFuncSetAttribute(attn_f16_kernel,
                             cudaFuncAttributeMaxDynamicSharedMemorySize, ASMEM_DYN);
        dim3 grid(S_LEN / 128, H_NUM);
        attn_f16_kernel<<<grid, 256, ASMEM_DYN>>>(
            qp_p, kp_p, (const uint32_t*)vp_p, att_p);
    }

    // 3) proj GEMM -> fp32 out
    {
        dim3 grid(C_DIM / 128, S_LEN / 128);
        gemm_f16_kernel<0><<<grid, 128, GSMEM_DYN>>>(
            S_LEN, C_DIM, C_DIM, att_p, wpp_p, b_proj,
            out, nullptr, nullptr, nullptr);
    }
}

// round 14
// speedup vs baseline: 1.0920x; 1.0920x over previous
#include <cuda_runtime.h>
#include <cuda_fp16.h>
#include <cstdint>
#include <math.h>

#define S_LEN 4096
#define C_DIM 1024
#define H_NUM 16
#define HD    64
// Q pre-scale: 1/sqrt(64) * log2(e)  (softmax runs in exp2 domain)
#define QSCALE 0.18033688011112042f

// Scratch (__device__ globals). All mma-fragment-packed, fp16.
__device__ uint32_t g_qp [(size_t)H_NUM * 256 * 4 * 32 * 4];   // Q A-perm16 per head
__device__ uint32_t g_kp [(size_t)H_NUM * 512 * 4 * 32 * 2];   // K B-perm16 per head
__device__ __half   g_vp [(size_t)H_NUM * 256 * 8 * 32 * 4];   // V B-perm16 (kv-major)
__device__ uint32_t g_att[(size_t)256 * 64 * 32 * 4];          // attn out, A-perm16
__device__ uint32_t g_xp [(size_t)256 * 64 * 32 * 4];          // x, A-perm16
__device__ uint32_t g_wtp[(size_t)384 * 64 * 32 * 2];          // W_attn B-perm16 (Q pre-scaled)
__device__ uint32_t g_wpp[(size_t)128 * 64 * 32 * 2];          // W_proj B-perm16

// ---------------------------------------------------------------------------
__device__ __forceinline__ void cp16(void* s, const void* g) {
    uint32_t sa = (uint32_t)__cvta_generic_to_shared(s);
    asm volatile("cp.async.cg.shared.global [%0], [%1], 16;"
                 :: "r"(sa), "l"(__cvta_generic_to_global(g)));
}

__device__ __forceinline__ uint32_t h2u(__half2 h) {
    return *reinterpret_cast<uint32_t*>(&h);
}

__device__ __forceinline__ float ex2(float x) {
    float y;
    asm("ex2.approx.ftz.f32 %0, %1;" : "=f"(y) : "f"(x));
    return y;
}

// m16n8k16 fp16 mma, fp32 accum. A row-major, B col-major.
__device__ __forceinline__ void mma_f16(float c[4], const uint32_t a[4],
                                        uint32_t b0, uint32_t b1) {
    asm volatile(
        "mma.sync.aligned.m16n8k16.row.col.f32.f16.f16.f32 "
        "{%0,%1,%2,%3}, {%4,%5,%6,%7}, {%8,%9}, {%0,%1,%2,%3};"
        : "+f"(c[0]), "+f"(c[1]), "+f"(c[2]), "+f"(c[3])
        : "r"(a[0]), "r"(a[1]), "r"(a[2]), "r"(a[3]), "r"(b0), "r"(b1));
}

// ---------------------------------------------------------------------------
// Prep: A-perm16 of x [M,K]f32 -> [mb][kb16][lane][4xb32(h2)]
// ---------------------------------------------------------------------------
__global__ __launch_bounds__(256) void permA16_kernel(
    const float* __restrict__ in, uint32_t* __restrict__ out, int M, int K)
{
    int cid = blockIdx.x * 256 + threadIdx.x;
    if (cid >= (M / 16) * (K / 16) * 32) return;
    const int per_mb = (K >> 4) * 32;
    int mb  = cid / per_mb;
    int rem = cid - mb * per_mb;
    int kb  = rem >> 5;
    int lane = rem & 31;
    int g = lane >> 2, q = lane & 3;
    size_t r = mb * 16 + g, c = kb * 16 + 2 * q;
    uint4 o;
    o.x = h2u(__floats2half2_rn(in[r * K + c],           in[r * K + c + 1]));
    o.y = h2u(__floats2half2_rn(in[(r + 8) * K + c],     in[(r + 8) * K + c + 1]));
    o.z = h2u(__floats2half2_rn(in[r * K + c + 8],       in[r * K + c + 9]));
    o.w = h2u(__floats2half2_rn(in[(r + 8) * K + c + 8], in[(r + 8) * K + c + 9]));
    ((uint4*)out)[cid] = o;
}

// ---------------------------------------------------------------------------
// Prep: B-perm16 of W [K][N] -> [nb][kb16][lane][2xb32]; cols n<scaleN *= scale
// ---------------------------------------------------------------------------
__global__ __launch_bounds__(256) void permB16_kernel(
    const float* __restrict__ W, uint32_t* __restrict__ out,
    int K, int N, int scaleN, float scale)
{
    int cid = blockIdx.x * 256 + threadIdx.x;
    if (cid >= (N / 8) * (K / 16) * 32) return;
    const int per_nb = (K >> 4) * 32;
    int nb  = cid / per_nb;
    int rem = cid - nb * per_nb;
    int kb  = rem >> 5;
    int lane = rem & 31;
    int g = lane >> 2, q = lane & 3;
    size_t n = nb * 8 + g, k = kb * 16 + 2 * q;
    float s = (n < (size_t)scaleN) ? scale : 1.f;
    uint2 o;
    o.x = h2u(__floats2half2_rn(W[k * N + n] * s,       W[(k + 1) * N + n] * s));
    o.y = h2u(__floats2half2_rn(W[(k + 8) * N + n] * s, W[(k + 9) * N + n] * s));
    ((uint2*)out)[cid] = o;
}

// ---------------------------------------------------------------------------
// fp16 mma.sync GEMM, CTA 128x128, 128 threads (4 warps 2x2), warp 64x64.
// BK=32 (2 kb16), 3-stage cp.async. (unchanged)
// ---------------------------------------------------------------------------
#define GSTAGE_U 4096
#define GSMEM_DYN (3 * GSTAGE_U * 4)

extern __shared__ uint32_t gsm[];

template<int MODE>
__global__ __launch_bounds__(128, 2) void gemm_f16_kernel(
    int M, int N, int K,
    const uint32_t* __restrict__ Ap,
    const uint32_t* __restrict__ Bp,
    const float* __restrict__ bias,
    float* __restrict__ C,
    uint32_t* __restrict__ Qp,
    uint32_t* __restrict__ Kp,
    __half* __restrict__ Vp)
{
    const int tid  = threadIdx.x;
    const int wid  = tid >> 5;
    const int lane = tid & 31;
    const int g    = lane >> 2, q = lane & 3;
    const int bm   = blockIdx.y * 128;
    const int bn   = blockIdx.x * 128;
    const int mb0  = (wid >> 1) * 4;
    const int nb0  = (wid & 1) * 8;
    const int KB   = K >> 4;
    const int nch  = K >> 5;

    float acc[4][8][4];
#pragma unroll
    for (int i = 0; i < 4; i++)
#pragma unroll
        for (int j = 0; j < 8; j++)
#pragma unroll
            for (int e = 0; e < 4; e++) acc[i][j][e] = 0.f;

    auto load_stage = [&](int s, int ch) {
        uint32_t* As = gsm + s * GSTAGE_U;
        uint32_t* Bs = As + 2048;
        const int kb0 = ch * 2;
#pragma unroll
        for (int it = 0; it < 4; it++) {
            int idx = tid + it * 128;
            int mb = idx >> 6, rem = idx & 63;
            int kb = rem >> 5, l = rem & 31;
            const uint32_t* src = Ap +
                ((size_t)((bm >> 4) + mb) * KB + kb0 + kb) * 128 + l * 4;
            cp16(As + idx * 4, src);
        }
#pragma unroll
        for (int it = 0; it < 4; it++) {
            int idx = tid + it * 128;
            int nb = idx >> 5, rem = idx & 31;
            int kb = rem >> 4, ll = rem & 15;
            const uint32_t* src = Bp +
                ((size_t)((bn >> 3) + nb) * KB + kb0 + kb) * 64 + ll * 4;
            cp16(Bs + idx * 4, src);
        }
        asm volatile("cp.async.commit_group;" ::: "memory");
    };

    load_stage(0, 0);
    load_stage(1, 1);

    for (int ch = 0; ch < nch; ch++) {
        if (ch + 2 < nch)
            asm volatile("cp.async.wait_group 1;" ::: "memory");
        else
            asm volatile("cp.async.wait_group 0;" ::: "memory");
        __syncthreads();

        if (ch + 2 < nch) load_stage((ch + 2) % 3, ch + 2);

        const uint32_t* As = gsm + (ch % 3) * GSTAGE_U;
        const uint32_t* Bs = As + 2048;

#pragma unroll
        for (int kb = 0; kb < 2; kb++) {
            uint4 afr[4];
            uint2 bfr[8];
#pragma unroll
            for (int i = 0; i < 4; i++)
                afr[i] = *(const uint4*)(As + ((mb0 + i) * 2 + kb) * 128 + lane * 4);
#pragma unroll
            for (int j = 0; j < 8; j++)
                bfr[j] = *(const uint2*)(Bs + ((nb0 + j) * 2 + kb) * 64 + lane * 2);
#pragma unroll
            for (int i = 0; i < 4; i++)
#pragma unroll
                for (int j = 0; j < 8; j++)
                    mma_f16(acc[i][j], (const uint32_t*)&afr[i], bfr[j].x, bfr[j].y);
        }
    }

    if (MODE == 0) {
#pragma unroll
        for (int j = 0; j < 8; j++) {
            const int col = bn + (wid & 1) * 64 + j * 8 + 2 * q;
            const float2 bv = *(const float2*)(bias + col);
#pragma unroll
            for (int i = 0; i < 4; i++) {
                const int r0 = bm + (wid >> 1) * 64 + i * 16 + g;
                float2 o0, o1;
                o0.x = acc[i][j][0] + bv.x;
                o0.y = acc[i][j][1] + bv.y;
                o1.x = acc[i][j][2] + bv.x;
                o1.y = acc[i][j][3] + bv.y;
                *(float2*)(C + (size_t)r0 * N + col) = o0;
                *(float2*)(C + (size_t)(r0 + 8) * N + col) = o1;
            }
        }
    } else {
        const int sec = bn >> 10;
        const int hh  = ((bn & 1023) >> 6) + (wid & 1);
        const float bscale = (sec == 0) ? QSCALE : 1.f;
#pragma unroll
        for (int j = 0; j < 8; j++) {
            const int col = bn + (wid & 1) * 64 + j * 8 + 2 * q;
            float2 bv = *(const float2*)(bias + col);
            bv.x *= bscale; bv.y *= bscale;
#pragma unroll
            for (int i = 0; i < 4; i++) {
                float v00 = acc[i][j][0] + bv.x;
                float v01 = acc[i][j][1] + bv.y;
                float v10 = acc[i][j][2] + bv.x;
                float v11 = acc[i][j][3] + bv.y;
                uint32_t p0 = h2u(__floats2half2_rn(v00, v01));
                uint32_t p1 = h2u(__floats2half2_rn(v10, v11));
                if (sec == 0) {
                    const int mb = (bm >> 4) + (wid >> 1) * 4 + i;
                    const int kb = j >> 1;
                    uint32_t* base = Qp +
                        (((size_t)(hh * 256 + mb) * 4 + kb) * 32 + lane) * 4 + (j & 1) * 2;
                    base[0] = p0;
                    base[1] = p1;
                } else if (sec == 1) {
                    const int nb = (bm >> 3) + (wid >> 1) * 8 + i * 2;
                    const int kb = j >> 1;
                    uint32_t* base = Kp +
                        (((size_t)(hh * 512 + nb) * 4 + kb) * 32 + lane) * 2 + (j & 1);
                    base[0]   = p0;
                    base[256] = p1;
                } else {
                    const int kvb = (bm >> 4) + (wid >> 1) * 4 + i;
                    const int hi  = g & 1;
                    __half* b0 = Vp +
                        ((((size_t)(hh * 256 + kvb) * 8 + j) * 32 + 2 * q * 4 + (g >> 1)) * 4);
                    __half* b1 = b0 + 16;
                    b0[hi]     = __float2half_rn(v00);
                    b0[2 + hi] = __float2half_rn(v10);
                    b1[hi]     = __float2half_rn(v01);
                    b1[2 + hi] = __float2half_rn(v11);
                }
            }
        }
    }
}

// ---------------------------------------------------------------------------
// Causal flash attention, fp16 m16n8k16, P in registers, exp2-domain softmax.
// SMALL-CTA HIGH-OCCUPANCY variant: CTA = (head, 64 q-rows), 128 threads
// (4 warps x 16-row strips), 2-stage shared KV ring (32 KB smem),
// __launch_bounds__(128,3) -> 3 CTAs/SM = 12 warps/SM, 3 independent rhythms.
// Per-warp math identical to round 12.
// ---------------------------------------------------------------------------
#define ASTG_U 4096                          // u32 per stage: K 2048 + V 2048
#define ASMEM_DYN (2 * ASTG_U * 4)           // 32768 B

extern __shared__ uint32_t asmem[];

__global__ __launch_bounds__(128, 3) void attn_f16_kernel(
    const uint32_t* __restrict__ Qp, const uint32_t* __restrict__ Kp,
    const uint32_t* __restrict__ Vp, uint32_t* __restrict__ att)
{
    const int tid   = threadIdx.x;
    const int warp  = tid >> 5;
    const int lane  = tid & 31;
    const int grp   = lane >> 2;
    const int qd    = lane & 3;
    const int h     = blockIdx.y;
    const int qtile = gridDim.x - 1 - blockIdx.x;   // big tiles first
    const int qbase = qtile * 64;
    const int qr0   = warp * 16 + grp;              // 0..63
    const int njt   = qtile + 1;                    // kv tiles of 64

    // ---- Q fragments: 4 x LDG.128 from packed Qp ----
    uint32_t qa[4][4];
    {
        const uint4* Qb = (const uint4*)(Qp +
            ((size_t)(h * 256 + qtile * 4 + warp) * 4) * 128);
#pragma unroll
        for (int ks = 0; ks < 4; ks++) {
            uint4 v = Qb[ks * 32 + lane];
            qa[ks][0] = v.x; qa[ks][1] = v.y; qa[ks][2] = v.z; qa[ks][3] = v.w;
        }
    }

    // shared load of tile jt into stage jt&1
    auto load_kv = [&](int jt) {
        uint32_t* Ks = asmem + (jt & 1) * ASTG_U;
        uint32_t* Vs = Ks + 2048;
        const uint32_t* Kg = Kp + (size_t)(h * 512 + jt * 8) * 256;
        const uint32_t* Vg = Vp + (size_t)(h * 256 + jt * 4) * 512;
#pragma unroll
        for (int it = 0; it < 4; it++) {
            int idx = tid + it * 128;
            cp16(Ks + idx * 4, Kg + idx * 4);
            cp16(Vs + idx * 4, Vg + idx * 4);
        }
        asm volatile("cp.async.commit_group;" ::: "memory");
    };

    load_kv(0);

    float o[8][4];
#pragma unroll
    for (int nt = 0; nt < 8; nt++)
#pragma unroll
        for (int e = 0; e < 4; e++) o[nt][e] = 0.f;
    float m0 = -INFINITY, m1 = -INFINITY, l0 = 0.f, l1 = 0.f;

    for (int jt = 0; jt < njt; jt++) {
        if (jt) __syncthreads();              // stage being overwritten is free
        if (jt + 1 < njt) load_kv(jt + 1);
        if (jt + 1 < njt)
            asm volatile("cp.async.wait_group 1;" ::: "memory");
        else
            asm volatile("cp.async.wait_group 0;" ::: "memory");
        __syncthreads();

        const uint32_t* Ks = asmem + (jt & 1) * ASTG_U;
        const uint32_t* Vs = Ks + 2048;
        const int kvbase = jt * 64;

        // ---- S = Q K^T ----
        float sv[8][4];
#pragma unroll
        for (int nt = 0; nt < 8; nt++)
#pragma unroll
            for (int e = 0; e < 4; e++) sv[nt][e] = 0.f;

#pragma unroll
        for (int ks = 0; ks < 4; ks++) {
#pragma unroll
            for (int nt = 0; nt < 8; nt++) {
                uint2 b = *(const uint2*)(Ks + ((nt * 4 + ks) * 32 + lane) * 2);
                mma_f16(sv[nt], qa[ks], b.x, b.y);
            }
        }

        // ---- causal mask (diagonal tile only) ----
        if (jt == qtile) {
            const int rg0 = qbase + qr0, rg1 = rg0 + 8;
#pragma unroll
            for (int nt = 0; nt < 8; nt++) {
                int cg = kvbase + nt * 8 + qd * 2;
                if (cg     > rg0) sv[nt][0] = -INFINITY;
                if (cg + 1 > rg0) sv[nt][1] = -INFINITY;
                if (cg     > rg1) sv[nt][2] = -INFINITY;
                if (cg + 1 > rg1) sv[nt][3] = -INFINITY;
            }
        }

        // ---- online softmax (exp2 domain) ----
        float mt0 = -INFINITY, mt1 = -INFINITY;
#pragma unroll
        for (int nt = 0; nt < 8; nt++) {
            mt0 = fmaxf(mt0, fmaxf(sv[nt][0], sv[nt][1]));
            mt1 = fmaxf(mt1, fmaxf(sv[nt][2], sv[nt][3]));
        }
        mt0 = fmaxf(mt0, __shfl_xor_sync(0xffffffffu, mt0, 1));
        mt0 = fmaxf(mt0, __shfl_xor_sync(0xffffffffu, mt0, 2));
        mt1 = fmaxf(mt1, __shfl_xor_sync(0xffffffffu, mt1, 1));
        mt1 = fmaxf(mt1, __shfl_xor_sync(0xffffffffu, mt1, 2));

        const float mn0 = fmaxf(m0, mt0), mn1 = fmaxf(m1, mt1);
        const float al0 = ex2(m0 - mn0), al1 = ex2(m1 - mn1);
        m0 = mn0; m1 = mn1;

        float rs0 = 0.f, rs1 = 0.f;
#pragma unroll
        for (int nt = 0; nt < 8; nt++) {
            sv[nt][0] = ex2(sv[nt][0] - mn0);
            sv[nt][1] = ex2(sv[nt][1] - mn0);
            sv[nt][2] = ex2(sv[nt][2] - mn1);
            sv[nt][3] = ex2(sv[nt][3] - mn1);
            rs0 += sv[nt][0] + sv[nt][1];
            rs1 += sv[nt][2] + sv[nt][3];
        }
        rs0 += __shfl_xor_sync(0xffffffffu, rs0, 1);
        rs0 += __shfl_xor_sync(0xffffffffu, rs0, 2);
        rs1 += __shfl_xor_sync(0xffffffffu, rs1, 1);
        rs1 += __shfl_xor_sync(0xffffffffu, rs1, 2);
        l0 = l0 * al0 + rs0;
        l1 = l1 * al1 + rs1;

#pragma unroll
        for (int nt = 0; nt < 8; nt++) {
            o[nt][0] *= al0; o[nt][1] *= al0;
            o[nt][2] *= al1; o[nt][3] *= al1;
        }

        // ---- P: pack C-frags directly into PV A-frags (registers only) ----
        uint32_t p0[8], p1[8];
#pragma unroll
        for (int nt = 0; nt < 8; nt++) {
            p0[nt] = h2u(__floats2half2_rn(sv[nt][0], sv[nt][1]));
            p1[nt] = h2u(__floats2half2_rn(sv[nt][2], sv[nt][3]));
        }

        // ---- O += P V ----
#pragma unroll
        for (int ks = 0; ks < 4; ks++) {
            uint32_t pa[4] = { p0[2 * ks], p1[2 * ks],
                               p0[2 * ks + 1], p1[2 * ks + 1] };
#pragma unroll
            for (int nt = 0; nt < 8; nt++) {
                uint2 b = *(const uint2*)(Vs + ((ks * 8 + nt) * 32 + lane) * 2);
                mma_f16(o[nt], pa, b.x, b.y);
            }
        }
    }

    // ---- epilogue: normalize + fp16 round, store g_att in A-perm16 ----
    const float i0 = 1.f / l0, i1 = 1.f / l1;
    const int mb = qtile * 4 + warp;
#pragma unroll
    for (int nt = 0; nt < 8; nt++) {
        const int kb = h * 4 + (nt >> 1);
        uint32_t* base = att +
            (((size_t)mb * 64 + kb) * 32 + lane) * 4 + (nt & 1) * 2;
        base[0] = h2u(__floats2half2_rn(o[nt][0] * i0, o[nt][1] * i0));
        base[1] = h2u(__floats2half2_rn(o[nt][2] * i1, o[nt][3] * i1));
    }
}

// ---------------------------------------------------------------------------
// Launch
// ---------------------------------------------------------------------------
extern "C" void kernel_launch(void* const* d_in, const int* in_sizes, int n_in,
                              void* d_out, int out_size)
{
    const float* x      = (const float*)d_in[0];
    // d_in[1] = attention_mask: exact causal triu -> handled analytically
    const float* W_attn = (const float*)d_in[2];
    const float* b_attn = (const float*)d_in[3];
    const float* W_proj = (const float*)d_in[4];
    const float* b_proj = (const float*)d_in[5];
    float* out = (float*)d_out;

    uint32_t *qp_p, *kp_p, *att_p, *xp_p, *wtp_p, *wpp_p;
    __half* vp_p;
    cudaGetSymbolAddress((void**)&qp_p,  g_qp);
    cudaGetSymbolAddress((void**)&kp_p,  g_kp);
    cudaGetSymbolAddress((void**)&vp_p,  g_vp);
    cudaGetSymbolAddress((void**)&att_p, g_att);
    cudaGetSymbolAddress((void**)&xp_p,  g_xp);
    cudaGetSymbolAddress((void**)&wtp_p, g_wtp);
    cudaGetSymbolAddress((void**)&wpp_p, g_wpp);

    // 0) prep: fp16 permuted operands (Q cols of W_attn get QSCALE)
    {
        int nA = 256 * 64 * 32;
        permA16_kernel<<<(nA + 255) / 256, 256>>>(x, xp_p, S_LEN, C_DIM);

        int nB1 = 384 * 64 * 32;
        permB16_kernel<<<(nB1 + 255) / 256, 256>>>(
            W_attn, wtp_p, C_DIM, 3 * C_DIM, C_DIM, QSCALE);

        int nB2 = 128 * 64 * 32;
        permB16_kernel<<<(nB2 + 255) / 256, 256>>>(
            W_proj, wpp_p, C_DIM, C_DIM, 0, 1.f);
    }

    cudaFuncSetAttribute(gemm_f16_kernel<0>,
                         cudaFuncAttributeMaxDynamicSharedMemorySize, GSMEM_DYN);
    cudaFuncSetAttribute(gemm_f16_kernel<1>,
                         cudaFuncAttributeMaxDynamicSharedMemorySize, GSMEM_DYN);

    // 1) qkv GEMM -> packed Qp/Kp/Vp
    {
        dim3 grid((3 * C_DIM) / 128, S_LEN / 128);
        gemm_f16_kernel<1><<<grid, 128, GSMEM_DYN>>>(
            S_LEN, 3 * C_DIM, C_DIM, xp_p, wtp_p, b_attn,
            nullptr, qp_p, kp_p, vp_p);
    }

    // 2) causal flash attention (64-row CTAs, 3 CTAs/SM)
    {
        cudaFuncSetAttribute(attn_f16_kernel,
                             cudaFuncAttributeMaxDynamicSharedMemorySize, ASMEM_DYN);
        dim3 grid(S_LEN / 64, H_NUM);
        attn_f16_kernel<<<grid, 128, ASMEM_DYN>>>(
            qp_p, kp_p, (const uint32_t*)vp_p, att_p);
    }

    // 3) proj GEMM -> fp32 out
    {
        dim3 grid(C_DIM / 128, S_LEN / 128);
        gemm_f16_kernel<0><<<grid, 128, GSMEM_DYN>>>(
            S_LEN, C_DIM, C_DIM, att_p, wpp_p, b_proj,
            out, nullptr, nullptr, nullptr);
    }
}

// round 15
// speedup vs baseline: 1.1355x; 1.0398x over previous
#include <cuda_runtime.h>
#include <cuda_fp16.h>
#include <cstdint>
#include <math.h>

#define S_LEN 4096
#define C_DIM 1024
#define H_NUM 16
#define HD    64
// Q pre-scale: 1/sqrt(64) * log2(e)  (softmax runs in exp2 domain)
#define QSCALE 0.18033688011112042f

// Scratch (__device__ globals). All mma-fragment-packed, fp16.
__device__ uint32_t g_qp [(size_t)H_NUM * 256 * 4 * 32 * 4];   // Q A-perm16 per head
__device__ uint32_t g_kp [(size_t)H_NUM * 512 * 4 * 32 * 2];   // K B-perm16 per head
__device__ __half   g_vp [(size_t)H_NUM * 256 * 8 * 32 * 4];   // V B-perm16 (kv-major)
__device__ uint32_t g_att[(size_t)256 * 64 * 32 * 4];          // attn out, A-perm16
__device__ uint32_t g_xp [(size_t)256 * 64 * 32 * 4];          // x, A-perm16
__device__ uint32_t g_wtp[(size_t)384 * 64 * 32 * 2];          // W_attn B-perm16 (Q pre-scaled)
__device__ uint32_t g_wpp[(size_t)128 * 64 * 32 * 2];          // W_proj B-perm16

// ---------------------------------------------------------------------------
__device__ __forceinline__ void cp16(void* s, const void* g) {
    uint32_t sa = (uint32_t)__cvta_generic_to_shared(s);
    asm volatile("cp.async.cg.shared.global [%0], [%1], 16;"
                 :: "r"(sa), "l"(__cvta_generic_to_global(g)));
}

__device__ __forceinline__ uint32_t h2u(__half2 h) {
    return *reinterpret_cast<uint32_t*>(&h);
}

__device__ __forceinline__ float ex2(float x) {
    float y;
    asm("ex2.approx.ftz.f32 %0, %1;" : "=f"(y) : "f"(x));
    return y;
}

// m16n8k16 fp16 mma, fp32 accum. A row-major, B col-major.
__device__ __forceinline__ void mma_f16(float c[4], const uint32_t a[4],
                                        uint32_t b0, uint32_t b1) {
    asm volatile(
        "mma.sync.aligned.m16n8k16.row.col.f32.f16.f16.f32 "
        "{%0,%1,%2,%3}, {%4,%5,%6,%7}, {%8,%9}, {%0,%1,%2,%3};"
        : "+f"(c[0]), "+f"(c[1]), "+f"(c[2]), "+f"(c[3])
        : "r"(a[0]), "r"(a[1]), "r"(a[2]), "r"(a[3]), "r"(b0), "r"(b1));
}

// ---------------------------------------------------------------------------
// Fused prep: one launch does
//   [0, NA)        : A-perm16 of x            (uint4 items)
//   [NA, NA+NB1)   : B-perm16 of W_attn (Q cols * QSCALE)  (uint2 items)
//   [NA+NB1, ...)  : B-perm16 of W_proj       (uint2 items)
// ---------------------------------------------------------------------------
#define PREP_NA  (256 * 64 * 32)
#define PREP_NB1 (384 * 64 * 32)
#define PREP_NB2 (128 * 64 * 32)
#define PREP_TOT (PREP_NA + PREP_NB1 + PREP_NB2)

__global__ __launch_bounds__(256) void prep_all_kernel(
    const float* __restrict__ x,
    const float* __restrict__ W_attn,
    const float* __restrict__ W_proj,
    uint32_t* __restrict__ xp,
    uint32_t* __restrict__ wtp,
    uint32_t* __restrict__ wpp)
{
    int gid = blockIdx.x * 256 + threadIdx.x;
    if (gid >= PREP_TOT) return;
    const int K = C_DIM;

    if (gid < PREP_NA) {
        // ---- A-perm16 of x: [mb][kb16][lane] -> uint4 ----
        const int per_mb = (K >> 4) * 32;     // 2048
        int mb  = gid / per_mb;
        int rem = gid - mb * per_mb;
        int kb  = rem >> 5;
        int lane = rem & 31;
        int g = lane >> 2, q = lane & 3;
        size_t r = mb * 16 + g, c = kb * 16 + 2 * q;
        uint4 o;
        o.x = h2u(__floats2half2_rn(x[r * K + c],           x[r * K + c + 1]));
        o.y = h2u(__floats2half2_rn(x[(r + 8) * K + c],     x[(r + 8) * K + c + 1]));
        o.z = h2u(__floats2half2_rn(x[r * K + c + 8],       x[r * K + c + 9]));
        o.w = h2u(__floats2half2_rn(x[(r + 8) * K + c + 8], x[(r + 8) * K + c + 9]));
        ((uint4*)xp)[gid] = o;
    } else {
        const float* W;
        uint32_t* out;
        int cid, N, scaleN;
        if (gid < PREP_NA + PREP_NB1) {
            cid = gid - PREP_NA;
            W = W_attn; out = wtp; N = 3 * C_DIM; scaleN = C_DIM;
        } else {
            cid = gid - PREP_NA - PREP_NB1;
            W = W_proj; out = wpp; N = C_DIM; scaleN = 0;
        }
        const int per_nb = (K >> 4) * 32;     // 2048
        int nb  = cid / per_nb;
        int rem = cid - nb * per_nb;
        int kb  = rem >> 5;
        int lane = rem & 31;
        int g = lane >> 2, q = lane & 3;
        size_t n = nb * 8 + g, k = kb * 16 + 2 * q;
        float s = (n < (size_t)scaleN) ? QSCALE : 1.f;
        uint2 o;
        o.x = h2u(__floats2half2_rn(W[k * N + n] * s,       W[(k + 1) * N + n] * s));
        o.y = h2u(__floats2half2_rn(W[(k + 8) * N + n] * s, W[(k + 9) * N + n] * s));
        ((uint2*)out)[cid] = o;
    }
}

// ---------------------------------------------------------------------------
// fp16 mma.sync GEMM, CTA 128x128, 128 threads (4 warps 2x2), warp 64x64.
// BK=32 (2 kb16), 3-stage cp.async. (unchanged)
// ---------------------------------------------------------------------------
#define GSTAGE_U 4096
#define GSMEM_DYN (3 * GSTAGE_U * 4)

extern __shared__ uint32_t gsm[];

template<int MODE>
__global__ __launch_bounds__(128, 2) void gemm_f16_kernel(
    int M, int N, int K,
    const uint32_t* __restrict__ Ap,
    const uint32_t* __restrict__ Bp,
    const float* __restrict__ bias,
    float* __restrict__ C,
    uint32_t* __restrict__ Qp,
    uint32_t* __restrict__ Kp,
    __half* __restrict__ Vp)
{
    const int tid  = threadIdx.x;
    const int wid  = tid >> 5;
    const int lane = tid & 31;
    const int g    = lane >> 2, q = lane & 3;
    const int bm   = blockIdx.y * 128;
    const int bn   = blockIdx.x * 128;
    const int mb0  = (wid >> 1) * 4;
    const int nb0  = (wid & 1) * 8;
    const int KB   = K >> 4;
    const int nch  = K >> 5;

    float acc[4][8][4];
#pragma unroll
    for (int i = 0; i < 4; i++)
#pragma unroll
        for (int j = 0; j < 8; j++)
#pragma unroll
            for (int e = 0; e < 4; e++) acc[i][j][e] = 0.f;

    auto load_stage = [&](int s, int ch) {
        uint32_t* As = gsm + s * GSTAGE_U;
        uint32_t* Bs = As + 2048;
        const int kb0 = ch * 2;
#pragma unroll
        for (int it = 0; it < 4; it++) {
            int idx = tid + it * 128;
            int mb = idx >> 6, rem = idx & 63;
            int kb = rem >> 5, l = rem & 31;
            const uint32_t* src = Ap +
                ((size_t)((bm >> 4) + mb) * KB + kb0 + kb) * 128 + l * 4;
            cp16(As + idx * 4, src);
        }
#pragma unroll
        for (int it = 0; it < 4; it++) {
            int idx = tid + it * 128;
            int nb = idx >> 5, rem = idx & 31;
            int kb = rem >> 4, ll = rem & 15;
            const uint32_t* src = Bp +
                ((size_t)((bn >> 3) + nb) * KB + kb0 + kb) * 64 + ll * 4;
            cp16(Bs + idx * 4, src);
        }
        asm volatile("cp.async.commit_group;" ::: "memory");
    };

    load_stage(0, 0);
    load_stage(1, 1);

    for (int ch = 0; ch < nch; ch++) {
        if (ch + 2 < nch)
            asm volatile("cp.async.wait_group 1;" ::: "memory");
        else
            asm volatile("cp.async.wait_group 0;" ::: "memory");
        __syncthreads();

        if (ch + 2 < nch) load_stage((ch + 2) % 3, ch + 2);

        const uint32_t* As = gsm + (ch % 3) * GSTAGE_U;
        const uint32_t* Bs = As + 2048;

#pragma unroll
        for (int kb = 0; kb < 2; kb++) {
            uint4 afr[4];
            uint2 bfr[8];
#pragma unroll
            for (int i = 0; i < 4; i++)
                afr[i] = *(const uint4*)(As + ((mb0 + i) * 2 + kb) * 128 + lane * 4);
#pragma unroll
            for (int j = 0; j < 8; j++)
                bfr[j] = *(const uint2*)(Bs + ((nb0 + j) * 2 + kb) * 64 + lane * 2);
#pragma unroll
            for (int i = 0; i < 4; i++)
#pragma unroll
                for (int j = 0; j < 8; j++)
                    mma_f16(acc[i][j], (const uint32_t*)&afr[i], bfr[j].x, bfr[j].y);
        }
    }

    if (MODE == 0) {
#pragma unroll
        for (int j = 0; j < 8; j++) {
            const int col = bn + (wid & 1) * 64 + j * 8 + 2 * q;
            const float2 bv = *(const float2*)(bias + col);
#pragma unroll
            for (int i = 0; i < 4; i++) {
                const int r0 = bm + (wid >> 1) * 64 + i * 16 + g;
                float2 o0, o1;
                o0.x = acc[i][j][0] + bv.x;
                o0.y = acc[i][j][1] + bv.y;
                o1.x = acc[i][j][2] + bv.x;
                o1.y = acc[i][j][3] + bv.y;
                *(float2*)(C + (size_t)r0 * N + col) = o0;
                *(float2*)(C + (size_t)(r0 + 8) * N + col) = o1;
            }
        }
    } else {
        const int sec = bn >> 10;
        const int hh  = ((bn & 1023) >> 6) + (wid & 1);
        const float bscale = (sec == 0) ? QSCALE : 1.f;
#pragma unroll
        for (int j = 0; j < 8; j++) {
            const int col = bn + (wid & 1) * 64 + j * 8 + 2 * q;
            float2 bv = *(const float2*)(bias + col);
            bv.x *= bscale; bv.y *= bscale;
#pragma unroll
            for (int i = 0; i < 4; i++) {
                float v00 = acc[i][j][0] + bv.x;
                float v01 = acc[i][j][1] + bv.y;
                float v10 = acc[i][j][2] + bv.x;
                float v11 = acc[i][j][3] + bv.y;
                uint32_t p0 = h2u(__floats2half2_rn(v00, v01));
                uint32_t p1 = h2u(__floats2half2_rn(v10, v11));
                if (sec == 0) {
                    const int mb = (bm >> 4) + (wid >> 1) * 4 + i;
                    const int kb = j >> 1;
                    uint32_t* base = Qp +
                        (((size_t)(hh * 256 + mb) * 4 + kb) * 32 + lane) * 4 + (j & 1) * 2;
                    base[0] = p0;
                    base[1] = p1;
                } else if (sec == 1) {
                    const int nb = (bm >> 3) + (wid >> 1) * 8 + i * 2;
                    const int kb = j >> 1;
                    uint32_t* base = Kp +
                        (((size_t)(hh * 512 + nb) * 4 + kb) * 32 + lane) * 2 + (j & 1);
                    base[0]   = p0;
                    base[256] = p1;
                } else {
                    const int kvb = (bm >> 4) + (wid >> 1) * 4 + i;
                    const int hi  = g & 1;
                    __half* b0 = Vp +
                        ((((size_t)(hh * 256 + kvb) * 8 + j) * 32 + 2 * q * 4 + (g >> 1)) * 4);
                    __half* b1 = b0 + 16;
                    b0[hi]     = __float2half_rn(v00);
                    b0[2 + hi] = __float2half_rn(v10);
                    b1[hi]     = __float2half_rn(v01);
                    b1[2 + hi] = __float2half_rn(v11);
                }
            }
        }
    }
}

// ---------------------------------------------------------------------------
// Causal flash attention, fp16 m16n8k16, P in registers, exp2-domain softmax.
// CTA = (head, 64 q-rows), 128 threads (4 warps x 16-row strips),
// 2-stage shared KV ring (32 KB smem), __launch_bounds__(128,4):
// 4 CTAs/SM = 16 warps/SM, 4 independent rhythms. Math identical to R14.
// ---------------------------------------------------------------------------
#define ASTG_U 4096                          // u32 per stage: K 2048 + V 2048
#define ASMEM_DYN (2 * ASTG_U * 4)           // 32768 B

extern __shared__ uint32_t asmem[];

__global__ __launch_bounds__(128, 4) void attn_f16_kernel(
    const uint32_t* __restrict__ Qp, const uint32_t* __restrict__ Kp,
    const uint32_t* __restrict__ Vp, uint32_t* __restrict__ att)
{
    const int tid   = threadIdx.x;
    const int warp  = tid >> 5;
    const int lane  = tid & 31;
    const int grp   = lane >> 2;
    const int qd    = lane & 3;
    const int h     = blockIdx.y;
    const int qtile = gridDim.x - 1 - blockIdx.x;   // big tiles first
    const int qbase = qtile * 64;
    const int qr0   = warp * 16 + grp;              // 0..63
    const int njt   = qtile + 1;                    // kv tiles of 64

    // ---- Q fragments: 4 x LDG.128 from packed Qp ----
    uint32_t qa[4][4];
    {
        const uint4* Qb = (const uint4*)(Qp +
            ((size_t)(h * 256 + qtile * 4 + warp) * 4) * 128);
#pragma unroll
        for (int ks = 0; ks < 4; ks++) {
            uint4 v = Qb[ks * 32 + lane];
            qa[ks][0] = v.x; qa[ks][1] = v.y; qa[ks][2] = v.z; qa[ks][3] = v.w;
        }
    }

    // shared load of tile jt into stage jt&1
    auto load_kv = [&](int jt) {
        uint32_t* Ks = asmem + (jt & 1) * ASTG_U;
        uint32_t* Vs = Ks + 2048;
        const uint32_t* Kg = Kp + (size_t)(h * 512 + jt * 8) * 256;
        const uint32_t* Vg = Vp + (size_t)(h * 256 + jt * 4) * 512;
#pragma unroll
        for (int it = 0; it < 4; it++) {
            int idx = tid + it * 128;
            cp16(Ks + idx * 4, Kg + idx * 4);
            cp16(Vs + idx * 4, Vg + idx * 4);
        }
        asm volatile("cp.async.commit_group;" ::: "memory");
    };

    load_kv(0);

    float o[8][4];
#pragma unroll
    for (int nt = 0; nt < 8; nt++)
#pragma unroll
        for (int e = 0; e < 4; e++) o[nt][e] = 0.f;
    float m0 = -INFINITY, m1 = -INFINITY, l0 = 0.f, l1 = 0.f;

    for (int jt = 0; jt < njt; jt++) {
        if (jt) __syncthreads();              // stage being overwritten is free
        if (jt + 1 < njt) load_kv(jt + 1);
        if (jt + 1 < njt)
            asm volatile("cp.async.wait_group 1;" ::: "memory");
        else
            asm volatile("cp.async.wait_group 0;" ::: "memory");
        __syncthreads();

        const uint32_t* Ks = asmem + (jt & 1) * ASTG_U;
        const uint32_t* Vs = Ks + 2048;
        const int kvbase = jt * 64;

        // ---- S = Q K^T ----
        float sv[8][4];
#pragma unroll
        for (int nt = 0; nt < 8; nt++)
#pragma unroll
            for (int e = 0; e < 4; e++) sv[nt][e] = 0.f;

#pragma unroll
        for (int ks = 0; ks < 4; ks++) {
#pragma unroll
            for (int nt = 0; nt < 8; nt++) {
                uint2 b = *(const uint2*)(Ks + ((nt * 4 + ks) * 32 + lane) * 2);
                mma_f16(sv[nt], qa[ks], b.x, b.y);
            }
        }

        // ---- causal mask (diagonal tile only) ----
        if (jt == qtile) {
            const int rg0 = qbase + qr0, rg1 = rg0 + 8;
#pragma unroll
            for (int nt = 0; nt < 8; nt++) {
                int cg = kvbase + nt * 8 + qd * 2;
                if (cg     > rg0) sv[nt][0] = -INFINITY;
                if (cg + 1 > rg0) sv[nt][1] = -INFINITY;
                if (cg     > rg1) sv[nt][2] = -INFINITY;
                if (cg + 1 > rg1) sv[nt][3] = -INFINITY;
            }
        }

        // ---- online softmax (exp2 domain) ----
        float mt0 = -INFINITY, mt1 = -INFINITY;
#pragma unroll
        for (int nt = 0; nt < 8; nt++) {
            mt0 = fmaxf(mt0, fmaxf(sv[nt][0], sv[nt][1]));
            mt1 = fmaxf(mt1, fmaxf(sv[nt][2], sv[nt][3]));
        }
        mt0 = fmaxf(mt0, __shfl_xor_sync(0xffffffffu, mt0, 1));
        mt0 = fmaxf(mt0, __shfl_xor_sync(0xffffffffu, mt0, 2));
        mt1 = fmaxf(mt1, __shfl_xor_sync(0xffffffffu, mt1, 1));
        mt1 = fmaxf(mt1, __shfl_xor_sync(0xffffffffu, mt1, 2));

        const float mn0 = fmaxf(m0, mt0), mn1 = fmaxf(m1, mt1);
        const float al0 = ex2(m0 - mn0), al1 = ex2(m1 - mn1);
        m0 = mn0; m1 = mn1;

        float rs0 = 0.f, rs1 = 0.f;
#pragma unroll
        for (int nt = 0; nt < 8; nt++) {
            sv[nt][0] = ex2(sv[nt][0] - mn0);
            sv[nt][1] = ex2(sv[nt][1] - mn0);
            sv[nt][2] = ex2(sv[nt][2] - mn1);
            sv[nt][3] = ex2(sv[nt][3] - mn1);
            rs0 += sv[nt][0] + sv[nt][1];
            rs1 += sv[nt][2] + sv[nt][3];
        }
        rs0 += __shfl_xor_sync(0xffffffffu, rs0, 1);
        rs0 += __shfl_xor_sync(0xffffffffu, rs0, 2);
        rs1 += __shfl_xor_sync(0xffffffffu, rs1, 1);
        rs1 += __shfl_xor_sync(0xffffffffu, rs1, 2);
        l0 = l0 * al0 + rs0;
        l1 = l1 * al1 + rs1;

#pragma unroll
        for (int nt = 0; nt < 8; nt++) {
            o[nt][0] *= al0; o[nt][1] *= al0;
            o[nt][2] *= al1; o[nt][3] *= al1;
        }

        // ---- P: pack C-frags directly into PV A-frags (registers only) ----
        uint32_t p0[8], p1[8];
#pragma unroll
        for (int nt = 0; nt < 8; nt++) {
            p0[nt] = h2u(__floats2half2_rn(sv[nt][0], sv[nt][1]));
            p1[nt] = h2u(__floats2half2_rn(sv[nt][2], sv[nt][3]));
        }

        // ---- O += P V ----
#pragma unroll
        for (int ks = 0; ks < 4; ks++) {
            uint32_t pa[4] = { p0[2 * ks], p1[2 * ks],
                               p0[2 * ks + 1], p1[2 * ks + 1] };
#pragma unroll
            for (int nt = 0; nt < 8; nt++) {
                uint2 b = *(const uint2*)(Vs + ((ks * 8 + nt) * 32 + lane) * 2);
                mma_f16(o[nt], pa, b.x, b.y);
            }
        }
    }

    // ---- epilogue: normalize + fp16 round, store g_att in A-perm16 ----
    const float i0 = 1.f / l0, i1 = 1.f / l1;
    const int mb = qtile * 4 + warp;
#pragma unroll
    for (int nt = 0; nt < 8; nt++) {
        const int kb = h * 4 + (nt >> 1);
        uint32_t* base = att +
            (((size_t)mb * 64 + kb) * 32 + lane) * 4 + (nt & 1) * 2;
        base[0] = h2u(__floats2half2_rn(o[nt][0] * i0, o[nt][1] * i0));
        base[1] = h2u(__floats2half2_rn(o[nt][2] * i1, o[nt][3] * i1));
    }
}

// ---------------------------------------------------------------------------
// Launch
// ---------------------------------------------------------------------------
extern "C" void kernel_launch(void* const* d_in, const int* in_sizes, int n_in,
                              void* d_out, int out_size)
{
    const float* x      = (const float*)d_in[0];
    // d_in[1] = attention_mask: exact causal triu -> handled analytically
    const float* W_attn = (const float*)d_in[2];
    const float* b_attn = (const float*)d_in[3];
    const float* W_proj = (const float*)d_in[4];
    const float* b_proj = (const float*)d_in[5];
    float* out = (float*)d_out;

    uint32_t *qp_p, *kp_p, *att_p, *xp_p, *wtp_p, *wpp_p;
    __half* vp_p;
    cudaGetSymbolAddress((void**)&qp_p,  g_qp);
    cudaGetSymbolAddress((void**)&kp_p,  g_kp);
    cudaGetSymbolAddress((void**)&vp_p,  g_vp);
    cudaGetSymbolAddress((void**)&att_p, g_att);
    cudaGetSymbolAddress((void**)&xp_p,  g_xp);
    cudaGetSymbolAddress((void**)&wtp_p, g_wtp);
    cudaGetSymbolAddress((void**)&wpp_p, g_wpp);

    // 0) fused prep (x + both weights, single launch)
    {
        prep_all_kernel<<<(PREP_TOT + 255) / 256, 256>>>(
            x, W_attn, W_proj, xp_p, wtp_p, wpp_p);
    }

    cudaFuncSetAttribute(gemm_f16_kernel<0>,
                         cudaFuncAttributeMaxDynamicSharedMemorySize, GSMEM_DYN);
    cudaFuncSetAttribute(gemm_f16_kernel<1>,
                         cudaFuncAttributeMaxDynamicSharedMemorySize, GSMEM_DYN);

    // 1) qkv GEMM -> packed Qp/Kp/Vp
    {
        dim3 grid((3 * C_DIM) / 128, S_LEN / 128);
        gemm_f16_kernel<1><<<grid, 128, GSMEM_DYN>>>(
            S_LEN, 3 * C_DIM, C_DIM, xp_p, wtp_p, b_attn,
            nullptr, qp_p, kp_p, vp_p);
    }

    // 2) causal flash attention (64-row CTAs, 4 CTAs/SM)
    {
        cudaFuncSetAttribute(attn_f16_kernel,
                             cudaFuncAttributeMaxDynamicSharedMemorySize, ASMEM_DYN);
        dim3 grid(S_LEN / 64, H_NUM);
        attn_f16_kernel<<<grid, 128, ASMEM_DYN>>>(
            qp_p, kp_p, (const uint32_t*)vp_p, att_p);
    }

    // 3) proj GEMM -> fp32 out
    {
        dim3 grid(C_DIM / 128, S_LEN / 128);
        gemm_f16_kernel<0><<<grid, 128, GSMEM_DYN>>>(
            S_LEN, C_DIM, C_DIM, att_p, wpp_p, b_proj,
            out, nullptr, nullptr, nullptr);
    }
}

// round 16
// speedup vs baseline: 1.1443x; 1.0077x over previous
#include <cuda_runtime.h>
#include <cuda_fp16.h>
#include <cstdint>
#include <math.h>

#define S_LEN 4096
#define C_DIM 1024
#define H_NUM 16
#define HD    64
// Q pre-scale: 1/sqrt(64) * log2(e)  (softmax runs in exp2 domain)
#define QSCALE 0.18033688011112042f

// Scratch (__device__ globals). All mma-fragment-packed, fp16.
__device__ uint32_t g_qp [(size_t)H_NUM * 256 * 4 * 32 * 4];   // Q A-perm16 per head
__device__ uint32_t g_kp [(size_t)H_NUM * 512 * 4 * 32 * 2];   // K B-perm16 per head
__device__ __half   g_vp [(size_t)H_NUM * 256 * 8 * 32 * 4];   // V B-perm16 (kv-major)
__device__ uint32_t g_att[(size_t)256 * 64 * 32 * 4];          // attn out, A-perm16
__device__ uint32_t g_xp [(size_t)256 * 64 * 32 * 4];          // x, A-perm16
__device__ uint32_t g_wtp[(size_t)384 * 64 * 32 * 2];          // W_attn B-perm16 (Q pre-scaled)
__device__ uint32_t g_wpp[(size_t)128 * 64 * 32 * 2];          // W_proj B-perm16

// ---------------------------------------------------------------------------
__device__ __forceinline__ void cp16(void* s, const void* g) {
    uint32_t sa = (uint32_t)__cvta_generic_to_shared(s);
    asm volatile("cp.async.cg.shared.global [%0], [%1], 16;"
                 :: "r"(sa), "l"(__cvta_generic_to_global(g)));
}

__device__ __forceinline__ uint32_t h2u(__half2 h) {
    return *reinterpret_cast<uint32_t*>(&h);
}

__device__ __forceinline__ float ex2(float x) {
    float y;
    asm("ex2.approx.ftz.f32 %0, %1;" : "=f"(y) : "f"(x));
    return y;
}

// m16n8k16 fp16 mma, fp32 accum. A row-major, B col-major.
__device__ __forceinline__ void mma_f16(float c[4], const uint32_t a[4],
                                        uint32_t b0, uint32_t b1) {
    asm volatile(
        "mma.sync.aligned.m16n8k16.row.col.f32.f16.f16.f32 "
        "{%0,%1,%2,%3}, {%4,%5,%6,%7}, {%8,%9}, {%0,%1,%2,%3};"
        : "+f"(c[0]), "+f"(c[1]), "+f"(c[2]), "+f"(c[3])
        : "r"(a[0]), "r"(a[1]), "r"(a[2]), "r"(a[3]), "r"(b0), "r"(b1));
}

// ---------------------------------------------------------------------------
// Fused prep: one launch does A-perm16(x) + B-perm16(W_attn,*QSCALE on Q cols)
// + B-perm16(W_proj).
// ---------------------------------------------------------------------------
#define PREP_NA  (256 * 64 * 32)
#define PREP_NB1 (384 * 64 * 32)
#define PREP_NB2 (128 * 64 * 32)
#define PREP_TOT (PREP_NA + PREP_NB1 + PREP_NB2)

__global__ __launch_bounds__(256) void prep_all_kernel(
    const float* __restrict__ x,
    const float* __restrict__ W_attn,
    const float* __restrict__ W_proj,
    uint32_t* __restrict__ xp,
    uint32_t* __restrict__ wtp,
    uint32_t* __restrict__ wpp)
{
    int gid = blockIdx.x * 256 + threadIdx.x;
    if (gid >= PREP_TOT) return;
    const int K = C_DIM;

    if (gid < PREP_NA) {
        const int per_mb = (K >> 4) * 32;
        int mb  = gid / per_mb;
        int rem = gid - mb * per_mb;
        int kb  = rem >> 5;
        int lane = rem & 31;
        int g = lane >> 2, q = lane & 3;
        size_t r = mb * 16 + g, c = kb * 16 + 2 * q;
        uint4 o;
        o.x = h2u(__floats2half2_rn(x[r * K + c],           x[r * K + c + 1]));
        o.y = h2u(__floats2half2_rn(x[(r + 8) * K + c],     x[(r + 8) * K + c + 1]));
        o.z = h2u(__floats2half2_rn(x[r * K + c + 8],       x[r * K + c + 9]));
        o.w = h2u(__floats2half2_rn(x[(r + 8) * K + c + 8], x[(r + 8) * K + c + 9]));
        ((uint4*)xp)[gid] = o;
    } else {
        const float* W;
        uint32_t* out;
        int cid, N, scaleN;
        if (gid < PREP_NA + PREP_NB1) {
            cid = gid - PREP_NA;
            W = W_attn; out = wtp; N = 3 * C_DIM; scaleN = C_DIM;
        } else {
            cid = gid - PREP_NA - PREP_NB1;
            W = W_proj; out = wpp; N = C_DIM; scaleN = 0;
        }
        const int per_nb = (K >> 4) * 32;
        int nb  = cid / per_nb;
        int rem = cid - nb * per_nb;
        int kb  = rem >> 5;
        int lane = rem & 31;
        int g = lane >> 2, q = lane & 3;
        size_t n = nb * 8 + g, k = kb * 16 + 2 * q;
        float s = (n < (size_t)scaleN) ? QSCALE : 1.f;
        uint2 o;
        o.x = h2u(__floats2half2_rn(W[k * N + n] * s,       W[(k + 1) * N + n] * s));
        o.y = h2u(__floats2half2_rn(W[(k + 8) * N + n] * s, W[(k + 9) * N + n] * s));
        ((uint2*)out)[cid] = o;
    }
}

// ---------------------------------------------------------------------------
// fp16 mma.sync GEMM, CTA 128x128, 128 threads (4 warps 2x2), warp 64x64.
// BK=32 (2 kb16), 3-stage cp.async. (unchanged)
// ---------------------------------------------------------------------------
#define GSTAGE_U 4096
#define GSMEM_DYN (3 * GSTAGE_U * 4)

extern __shared__ uint32_t gsm[];

template<int MODE>
__global__ __launch_bounds__(128, 2) void gemm_f16_kernel(
    int M, int N, int K,
    const uint32_t* __restrict__ Ap,
    const uint32_t* __restrict__ Bp,
    const float* __restrict__ bias,
    float* __restrict__ C,
    uint32_t* __restrict__ Qp,
    uint32_t* __restrict__ Kp,
    __half* __restrict__ Vp)
{
    const int tid  = threadIdx.x;
    const int wid  = tid >> 5;
    const int lane = tid & 31;
    const int g    = lane >> 2, q = lane & 3;
    const int bm   = blockIdx.y * 128;
    const int bn   = blockIdx.x * 128;
    const int mb0  = (wid >> 1) * 4;
    const int nb0  = (wid & 1) * 8;
    const int KB   = K >> 4;
    const int nch  = K >> 5;

    float acc[4][8][4];
#pragma unroll
    for (int i = 0; i < 4; i++)
#pragma unroll
        for (int j = 0; j < 8; j++)
#pragma unroll
            for (int e = 0; e < 4; e++) acc[i][j][e] = 0.f;

    auto load_stage = [&](int s, int ch) {
        uint32_t* As = gsm + s * GSTAGE_U;
        uint32_t* Bs = As + 2048;
        const int kb0 = ch * 2;
#pragma unroll
        for (int it = 0; it < 4; it++) {
            int idx = tid + it * 128;
            int mb = idx >> 6, rem = idx & 63;
            int kb = rem >> 5, l = rem & 31;
            const uint32_t* src = Ap +
                ((size_t)((bm >> 4) + mb) * KB + kb0 + kb) * 128 + l * 4;
            cp16(As + idx * 4, src);
        }
#pragma unroll
        for (int it = 0; it < 4; it++) {
            int idx = tid + it * 128;
            int nb = idx >> 5, rem = idx & 31;
            int kb = rem >> 4, ll = rem & 15;
            const uint32_t* src = Bp +
                ((size_t)((bn >> 3) + nb) * KB + kb0 + kb) * 64 + ll * 4;
            cp16(Bs + idx * 4, src);
        }
        asm volatile("cp.async.commit_group;" ::: "memory");
    };

    load_stage(0, 0);
    load_stage(1, 1);

    for (int ch = 0; ch < nch; ch++) {
        if (ch + 2 < nch)
            asm volatile("cp.async.wait_group 1;" ::: "memory");
        else
            asm volatile("cp.async.wait_group 0;" ::: "memory");
        __syncthreads();

        if (ch + 2 < nch) load_stage((ch + 2) % 3, ch + 2);

        const uint32_t* As = gsm + (ch % 3) * GSTAGE_U;
        const uint32_t* Bs = As + 2048;

#pragma unroll
        for (int kb = 0; kb < 2; kb++) {
            uint4 afr[4];
            uint2 bfr[8];
#pragma unroll
            for (int i = 0; i < 4; i++)
                afr[i] = *(const uint4*)(As + ((mb0 + i) * 2 + kb) * 128 + lane * 4);
#pragma unroll
            for (int j = 0; j < 8; j++)
                bfr[j] = *(const uint2*)(Bs + ((nb0 + j) * 2 + kb) * 64 + lane * 2);
#pragma unroll
            for (int i = 0; i < 4; i++)
#pragma unroll
                for (int j = 0; j < 8; j++)
                    mma_f16(acc[i][j], (const uint32_t*)&afr[i], bfr[j].x, bfr[j].y);
        }
    }

    if (MODE == 0) {
#pragma unroll
        for (int j = 0; j < 8; j++) {
            const int col = bn + (wid & 1) * 64 + j * 8 + 2 * q;
            const float2 bv = *(const float2*)(bias + col);
#pragma unroll
            for (int i = 0; i < 4; i++) {
                const int r0 = bm + (wid >> 1) * 64 + i * 16 + g;
                float2 o0, o1;
                o0.x = acc[i][j][0] + bv.x;
                o0.y = acc[i][j][1] + bv.y;
                o1.x = acc[i][j][2] + bv.x;
                o1.y = acc[i][j][3] + bv.y;
                *(float2*)(C + (size_t)r0 * N + col) = o0;
                *(float2*)(C + (size_t)(r0 + 8) * N + col) = o1;
            }
        }
    } else {
        const int sec = bn >> 10;
        const int hh  = ((bn & 1023) >> 6) + (wid & 1);
        const float bscale = (sec == 0) ? QSCALE : 1.f;
#pragma unroll
        for (int j = 0; j < 8; j++) {
            const int col = bn + (wid & 1) * 64 + j * 8 + 2 * q;
            float2 bv = *(const float2*)(bias + col);
            bv.x *= bscale; bv.y *= bscale;
#pragma unroll
            for (int i = 0; i < 4; i++) {
                float v00 = acc[i][j][0] + bv.x;
                float v01 = acc[i][j][1] + bv.y;
                float v10 = acc[i][j][2] + bv.x;
                float v11 = acc[i][j][3] + bv.y;
                uint32_t p0 = h2u(__floats2half2_rn(v00, v01));
                uint32_t p1 = h2u(__floats2half2_rn(v10, v11));
                if (sec == 0) {
                    const int mb = (bm >> 4) + (wid >> 1) * 4 + i;
                    const int kb = j >> 1;
                    uint32_t* base = Qp +
                        (((size_t)(hh * 256 + mb) * 4 + kb) * 32 + lane) * 4 + (j & 1) * 2;
                    base[0] = p0;
                    base[1] = p1;
                } else if (sec == 1) {
                    const int nb = (bm >> 3) + (wid >> 1) * 8 + i * 2;
                    const int kb = j >> 1;
                    uint32_t* base = Kp +
                        (((size_t)(hh * 512 + nb) * 4 + kb) * 32 + lane) * 2 + (j & 1);
                    base[0]   = p0;
                    base[256] = p1;
                } else {
                    const int kvb = (bm >> 4) + (wid >> 1) * 4 + i;
                    const int hi  = g & 1;
                    __half* b0 = Vp +
                        ((((size_t)(hh * 256 + kvb) * 8 + j) * 32 + 2 * q * 4 + (g >> 1)) * 4);
                    __half* b1 = b0 + 16;
                    b0[hi]     = __float2half_rn(v00);
                    b0[2 + hi] = __float2half_rn(v10);
                    b1[hi]     = __float2half_rn(v01);
                    b1[2 + hi] = __float2half_rn(v11);
                }
            }
        }
    }
}

// ---------------------------------------------------------------------------
// Causal flash attention, fp16 m16n8k16, P in registers, exp2-domain softmax.
// CTA = (head, 64 q-rows), 128 threads (4 warps x 16-row strips),
// 3-stage shared KV ring (48 KB smem), ONE __syncthreads per round:
//   wait_group(1) -> bar -> issue load(jt+2) -> compute(jt)
// __launch_bounds__(128,4): 4 CTAs/SM (192 KB smem), 16 warps/SM.
// Stage reuse: load(jt+2) overwrites tile jt-1, last read in round jt-1,
// protected by this round's bar.
// ---------------------------------------------------------------------------
#define ASTG_U 4096                          // u32 per stage: K 2048 + V 2048
#define ASMEM_DYN (3 * ASTG_U * 4)           // 49152 B

extern __shared__ uint32_t asmem[];

__global__ __launch_bounds__(128, 4) void attn_f16_kernel(
    const uint32_t* __restrict__ Qp, const uint32_t* __restrict__ Kp,
    const uint32_t* __restrict__ Vp, uint32_t* __restrict__ att)
{
    const int tid   = threadIdx.x;
    const int warp  = tid >> 5;
    const int lane  = tid & 31;
    const int grp   = lane >> 2;
    const int qd    = lane & 3;
    const int h     = blockIdx.y;
    const int qtile = gridDim.x - 1 - blockIdx.x;   // big tiles first
    const int qbase = qtile * 64;
    const int qr0   = warp * 16 + grp;              // 0..63
    const int njt   = qtile + 1;                    // kv tiles of 64

    // ---- Q fragments: 4 x LDG.128 from packed Qp ----
    uint32_t qa[4][4];
    {
        const uint4* Qb = (const uint4*)(Qp +
            ((size_t)(h * 256 + qtile * 4 + warp) * 4) * 128);
#pragma unroll
        for (int ks = 0; ks < 4; ks++) {
            uint4 v = Qb[ks * 32 + lane];
            qa[ks][0] = v.x; qa[ks][1] = v.y; qa[ks][2] = v.z; qa[ks][3] = v.w;
        }
    }

    // shared load of tile jt into stage jt%3 (empty commit past the end)
    auto load_kv = [&](int jt) {
        if (jt < njt) {
            uint32_t* Ks = asmem + (jt % 3) * ASTG_U;
            uint32_t* Vs = Ks + 2048;
            const uint32_t* Kg = Kp + (size_t)(h * 512 + jt * 8) * 256;
            const uint32_t* Vg = Vp + (size_t)(h * 256 + jt * 4) * 512;
#pragma unroll
            for (int it = 0; it < 4; it++) {
                int idx = tid + it * 128;
                cp16(Ks + idx * 4, Kg + idx * 4);
                cp16(Vs + idx * 4, Vg + idx * 4);
            }
        }
        asm volatile("cp.async.commit_group;" ::: "memory");
    };

    load_kv(0);
    load_kv(1);

    float o[8][4];
#pragma unroll
    for (int nt = 0; nt < 8; nt++)
#pragma unroll
        for (int e = 0; e < 4; e++) o[nt][e] = 0.f;
    float m0 = -INFINITY, m1 = -INFINITY, l0 = 0.f, l1 = 0.f;

    for (int jt = 0; jt < njt; jt++) {
        asm volatile("cp.async.wait_group 1;" ::: "memory");
        __syncthreads();
        load_kv(jt + 2);

        const uint32_t* Ks = asmem + (jt % 3) * ASTG_U;
        const uint32_t* Vs = Ks + 2048;
        const int kvbase = jt * 64;

        // ---- S = Q K^T ----
        float sv[8][4];
#pragma unroll
        for (int nt = 0; nt < 8; nt++)
#pragma unroll
            for (int e = 0; e < 4; e++) sv[nt][e] = 0.f;

#pragma unroll
        for (int ks = 0; ks < 4; ks++) {
#pragma unroll
            for (int nt = 0; nt < 8; nt++) {
                uint2 b = *(const uint2*)(Ks + ((nt * 4 + ks) * 32 + lane) * 2);
                mma_f16(sv[nt], qa[ks], b.x, b.y);
            }
        }

        // ---- causal mask (diagonal tile only) ----
        if (jt == qtile) {
            const int rg0 = qbase + qr0, rg1 = rg0 + 8;
#pragma unroll
            for (int nt = 0; nt < 8; nt++) {
                int cg = kvbase + nt * 8 + qd * 2;
                if (cg     > rg0) sv[nt][0] = -INFINITY;
                if (cg + 1 > rg0) sv[nt][1] = -INFINITY;
                if (cg     > rg1) sv[nt][2] = -INFINITY;
                if (cg + 1 > rg1) sv[nt][3] = -INFINITY;
            }
        }

        // ---- online softmax (exp2 domain) ----
        float mt0 = -INFINITY, mt1 = -INFINITY;
#pragma unroll
        for (int nt = 0; nt < 8; nt++) {
            mt0 = fmaxf(mt0, fmaxf(sv[nt][0], sv[nt][1]));
            mt1 = fmaxf(mt1, fmaxf(sv[nt][2], sv[nt][3]));
        }
        mt0 = fmaxf(mt0, __shfl_xor_sync(0xffffffffu, mt0, 1));
        mt0 = fmaxf(mt0, __shfl_xor_sync(0xffffffffu, mt0, 2));
        mt1 = fmaxf(mt1, __shfl_xor_sync(0xffffffffu, mt1, 1));
        mt1 = fmaxf(mt1, __shfl_xor_sync(0xffffffffu, mt1, 2));

        const float mn0 = fmaxf(m0, mt0), mn1 = fmaxf(m1, mt1);
        const float al0 = ex2(m0 - mn0), al1 = ex2(m1 - mn1);
        m0 = mn0; m1 = mn1;

        float rs0 = 0.f, rs1 = 0.f;
#pragma unroll
        for (int nt = 0; nt < 8; nt++) {
            sv[nt][0] = ex2(sv[nt][0] - mn0);
            sv[nt][1] = ex2(sv[nt][1] - mn0);
            sv[nt][2] = ex2(sv[nt][2] - mn1);
            sv[nt][3] = ex2(sv[nt][3] - mn1);
            rs0 += sv[nt][0] + sv[nt][1];
            rs1 += sv[nt][2] + sv[nt][3];
        }
        rs0 += __shfl_xor_sync(0xffffffffu, rs0, 1);
        rs0 += __shfl_xor_sync(0xffffffffu, rs0, 2);
        rs1 += __shfl_xor_sync(0xffffffffu, rs1, 1);
        rs1 += __shfl_xor_sync(0xffffffffu, rs1, 2);
        l0 = l0 * al0 + rs0;
        l1 = l1 * al1 + rs1;

#pragma unroll
        for (int nt = 0; nt < 8; nt++) {
            o[nt][0] *= al0; o[nt][1] *= al0;
            o[nt][2] *= al1; o[nt][3] *= al1;
        }

        // ---- P: pack C-frags directly into PV A-frags (registers only) ----
        uint32_t p0[8], p1[8];
#pragma unroll
        for (int nt = 0; nt < 8; nt++) {
            p0[nt] = h2u(__floats2half2_rn(sv[nt][0], sv[nt][1]));
            p1[nt] = h2u(__floats2half2_rn(sv[nt][2], sv[nt][3]));
        }

        // ---- O += P V ----
#pragma unroll
        for (int ks = 0; ks < 4; ks++) {
            uint32_t pa[4] = { p0[2 * ks], p1[2 * ks],
                               p0[2 * ks + 1], p1[2 * ks + 1] };
#pragma unroll
            for (int nt = 0; nt < 8; nt++) {
                uint2 b = *(const uint2*)(Vs + ((ks * 8 + nt) * 32 + lane) * 2);
                mma_f16(o[nt], pa, b.x, b.y);
            }
        }
    }

    // ---- epilogue: normalize + fp16 round, store g_att in A-perm16 ----
    const float i0 = 1.f / l0, i1 = 1.f / l1;
    const int mb = qtile * 4 + warp;
#pragma unroll
    for (int nt = 0; nt < 8; nt++) {
        const int kb = h * 4 + (nt >> 1);
        uint32_t* base = att +
            (((size_t)mb * 64 + kb) * 32 + lane) * 4 + (nt & 1) * 2;
        base[0] = h2u(__floats2half2_rn(o[nt][0] * i0, o[nt][1] * i0));
        base[1] = h2u(__floats2half2_rn(o[nt][2] * i1, o[nt][3] * i1));
    }
}

// ---------------------------------------------------------------------------
// Launch
// ---------------------------------------------------------------------------
extern "C" void kernel_launch(void* const* d_in, const int* in_sizes, int n_in,
                              void* d_out, int out_size)
{
    const float* x      = (const float*)d_in[0];
    // d_in[1] = attention_mask: exact causal triu -> handled analytically
    const float* W_attn = (const float*)d_in[2];
    const float* b_attn = (const float*)d_in[3];
    const float* W_proj = (const float*)d_in[4];
    const float* b_proj = (const float*)d_in[5];
    float* out = (float*)d_out;

    uint32_t *qp_p, *kp_p, *att_p, *xp_p, *wtp_p, *wpp_p;
    __half* vp_p;
    cudaGetSymbolAddress((void**)&qp_p,  g_qp);
    cudaGetSymbolAddress((void**)&kp_p,  g_kp);
    cudaGetSymbolAddress((void**)&vp_p,  g_vp);
    cudaGetSymbolAddress((void**)&att_p, g_att);
    cudaGetSymbolAddress((void**)&xp_p,  g_xp);
    cudaGetSymbolAddress((void**)&wtp_p, g_wtp);
    cudaGetSymbolAddress((void**)&wpp_p, g_wpp);

    // 0) fused prep (x + both weights, single launch)
    {
        prep_all_kernel<<<(PREP_TOT + 255) / 256, 256>>>(
            x, W_attn, W_proj, xp_p, wtp_p, wpp_p);
    }

    cudaFuncSetAttribute(gemm_f16_kernel<0>,
                         cudaFuncAttributeMaxDynamicSharedMemorySize, GSMEM_DYN);
    cudaFuncSetAttribute(gemm_f16_kernel<1>,
                         cudaFuncAttributeMaxDynamicSharedMemorySize, GSMEM_DYN);

    // 1) qkv GEMM -> packed Qp/Kp/Vp
    {
        dim3 grid((3 * C_DIM) / 128, S_LEN / 128);
        gemm_f16_kernel<1><<<grid, 128, GSMEM_DYN>>>(
            S_LEN, 3 * C_DIM, C_DIM, xp_p, wtp_p, b_attn,
            nullptr, qp_p, kp_p, vp_p);
    }

    // 2) causal flash attention (64-row CTAs, 4 CTAs/SM, 3-stage, 1 bar/round)
    {
        cudaFuncSetAttribute(attn_f16_kernel,
                             cudaFuncAttributeMaxDynamicSharedMemorySize, ASMEM_DYN);
        dim3 grid(S_LEN / 64, H_NUM);
        attn_f16_kernel<<<grid, 128, ASMEM_DYN>>>(
            qp_p, kp_p, (const uint32_t*)vp_p, att_p);
    }

    // 3) proj GEMM -> fp32 out
    {
        dim3 grid(C_DIM / 128, S_LEN / 128);
        gemm_f16_kernel<0><<<grid, 128, GSMEM_DYN>>>(
            S_LEN, C_DIM, C_DIM, att_p, wpp_p, b_proj,
            out, nullptr, nullptr, nullptr);
    }
}